// round 1
// baseline (speedup 1.0000x reference)
#include <cuda_runtime.h>
#include <math.h>

#define N_FRAMES 2048
#define N_AGENTS 32
#define N_ROWS (N_FRAMES * N_AGENTS)   // 65536
#define FEAT 512
#define HID 140
#define OUT2 256

// output layout: pred [65536,256] | a0 [65536,8] | a1 [65536,6] | a2 [65536,4]
#define OFF_A0 (N_ROWS * OUT2)            // 16777216
#define OFF_A1 (OFF_A0 + N_ROWS * 8)      // 17301504
#define OFF_A2 (OFF_A1 + N_ROWS * 6)      // 17694720

// scratch for hidden activations (36.7 MB), static device global (no alloc)
__device__ float g_hid[(size_t)N_ROWS * HID];

// ---------------------------------------------------------------------------
// Kernel 1: hid[M,140] = cur[M,512] @ W1[0:512,:] + onehot @ W1[512:530,:] + b1
// Block tile: BM=64, BN=140 (full), BK=32. Threads (20,8)=160. Thread tile 8x7.
// ---------------------------------------------------------------------------
__global__ __launch_bounds__(160) void fwd1_kernel(
    const float* __restrict__ cur, const int* __restrict__ actions,
    const float* __restrict__ W1, const float* __restrict__ b1)
{
    __shared__ float As[32][65];    // [k][row], padded
    __shared__ float Bs[32][140];   // [k][col]

    const int tx = threadIdx.x;     // 0..19  -> col group (7 cols)
    const int ty = threadIdx.y;     // 0..7   -> row group (8 rows)
    const int tid = ty * 20 + tx;
    const int row0 = blockIdx.x * 64;

    float acc[8][7];
    #pragma unroll
    for (int m = 0; m < 8; m++)
        #pragma unroll
        for (int n = 0; n < 7; n++) acc[m][n] = 0.f;

    for (int kb = 0; kb < 16; kb++) {
        // stage A tile: 64 rows x 32 k (coalesced along k)
        #pragma unroll
        for (int i = tid; i < 64 * 32; i += 160) {
            int r = i >> 5, k = i & 31;
            As[k][r] = cur[(size_t)(row0 + r) * FEAT + kb * 32 + k];
        }
        // stage B tile: 32 k x 140 cols (coalesced along n)
        #pragma unroll
        for (int i = tid; i < 32 * 140; i += 160) {
            int k = i / 140, n = i - k * 140;
            Bs[k][n] = W1[(size_t)(kb * 32 + k) * HID + n];
        }
        __syncthreads();

        #pragma unroll
        for (int k = 0; k < 32; k++) {
            float a[8], b[7];
            #pragma unroll
            for (int m = 0; m < 8; m++) a[m] = As[k][ty * 8 + m];
            #pragma unroll
            for (int n = 0; n < 7; n++) b[n] = Bs[k][tx * 7 + n];
            #pragma unroll
            for (int m = 0; m < 8; m++)
                #pragma unroll
                for (int n = 0; n < 7; n++)
                    acc[m][n] = fmaf(a[m], b[n], acc[m][n]);
        }
        __syncthreads();
    }

    // epilogue: + b1 + 3 one-hot rows of W1 (actions always in [0,4))
    #pragma unroll
    for (int m = 0; m < 8; m++) {
        int row = row0 + ty * 8 + m;
        int f = row >> 5, ag = row & 31;
        int i0 = actions[(f * 3 + 0) * N_AGENTS + ag];
        int i1 = actions[(f * 3 + 1) * N_AGENTS + ag];
        int i2 = actions[(f * 3 + 2) * N_AGENTS + ag];
        const float* w0 = W1 + (size_t)(FEAT + i0) * HID;
        const float* w1 = W1 + (size_t)(FEAT + 8 + i1) * HID;
        const float* w2 = W1 + (size_t)(FEAT + 14 + i2) * HID;
        #pragma unroll
        for (int n = 0; n < 7; n++) {
            int col = tx * 7 + n;
            g_hid[(size_t)row * HID + col] =
                acc[m][n] + b1[col] + w0[col] + w1[col] + w2[col];
        }
    }
}

// ---------------------------------------------------------------------------
// Kernel 2: pred[M,256] = hid[M,140] @ W2[140,256] + b2
// Block tile: BM=128, BN=64, BK=20 (140 = 7*20). Threads (8,16)=128. TT 8x8.
// ---------------------------------------------------------------------------
__global__ __launch_bounds__(128) void fwd2_kernel(
    const float* __restrict__ W2, const float* __restrict__ b2,
    float* __restrict__ out)
{
    __shared__ float As[20][129];   // [k][row], padded
    __shared__ float Bs[20][64];    // [k][col]

    const int tx = threadIdx.x;     // 0..7  -> col group (8 cols)
    const int ty = threadIdx.y;     // 0..15 -> row group (8 rows)
    const int tid = ty * 8 + tx;
    const int row0 = blockIdx.x * 128;
    const int col0 = blockIdx.y * 64;

    float acc[8][8];
    #pragma unroll
    for (int m = 0; m < 8; m++)
        #pragma unroll
        for (int n = 0; n < 8; n++) acc[m][n] = 0.f;

    for (int kb = 0; kb < 7; kb++) {
        #pragma unroll
        for (int i = tid; i < 128 * 20; i += 128) {
            int r = i / 20, k = i - r * 20;
            As[k][r] = g_hid[(size_t)(row0 + r) * HID + kb * 20 + k];
        }
        #pragma unroll
        for (int i = tid; i < 20 * 64; i += 128) {
            int k = i >> 6, n = i & 63;
            Bs[k][n] = W2[(size_t)(kb * 20 + k) * OUT2 + col0 + n];
        }
        __syncthreads();

        #pragma unroll
        for (int k = 0; k < 20; k++) {
            float a[8], b[8];
            #pragma unroll
            for (int m = 0; m < 8; m++) a[m] = As[k][ty * 8 + m];
            #pragma unroll
            for (int n = 0; n < 8; n++) b[n] = Bs[k][tx * 8 + n];
            #pragma unroll
            for (int m = 0; m < 8; m++)
                #pragma unroll
                for (int n = 0; n < 8; n++)
                    acc[m][n] = fmaf(a[m], b[n], acc[m][n]);
        }
        __syncthreads();
    }

    #pragma unroll
    for (int m = 0; m < 8; m++) {
        int row = row0 + ty * 8 + m;
        #pragma unroll
        for (int n = 0; n < 8; n++) {
            int col = col0 + tx * 8 + n;
            out[(size_t)row * OUT2 + col] = acc[m][n] + b2[col];
        }
    }
}

// ---------------------------------------------------------------------------
// Kernel 3: inverse dynamics + softmax over the AGENT axis.
// logits[row, 0:18] = [cur|next](row) @ [Wi0|Wi1|Wi2] + [bi0|bi1|bi2]
// softmax is over the 32 agents of each frame, per column, per group.
// One block per frame (32 rows). 8 warps x 4 rows/warp, K split over lanes.
// Wi staged to static smem in two K-halves (half0 = cur, half1 = next).
// ---------------------------------------------------------------------------
__global__ __launch_bounds__(256) void inv_kernel(
    const float* __restrict__ cur, const float* __restrict__ nxt,
    const float* __restrict__ Wi0, const float* __restrict__ bi0,
    const float* __restrict__ Wi1, const float* __restrict__ bi1,
    const float* __restrict__ Wi2, const float* __restrict__ bi2,
    float* __restrict__ out)
{
    __shared__ float Wis[512 * 19];   // [k][j], padded stride 19 (coprime w/ 32)
    __shared__ float logits[32 * 19]; // [agent][j]
    __shared__ float bis[18];

    const int tid = threadIdx.x;
    const int frame = blockIdx.x;
    const int w = tid >> 5, lane = tid & 31;
    const int rbase = frame * N_AGENTS + w * 4;

    if (tid < 8)       bis[tid] = bi0[tid];
    else if (tid < 14) bis[tid] = bi1[tid - 8];
    else if (tid < 18) bis[tid] = bi2[tid - 14];

    float acc[4][18];
    #pragma unroll
    for (int r = 0; r < 4; r++)
        #pragma unroll
        for (int j = 0; j < 18; j++) acc[r][j] = 0.f;

    const float* curb = cur + (size_t)rbase * FEAT;
    const float* nxtb = nxt + (size_t)rbase * FEAT;

    for (int half = 0; half < 2; half++) {
        // stage this K-half of the combined inverse weight matrix
        for (int i = tid; i < 512 * 8; i += 256) {
            int k = i >> 3, j = i & 7;
            Wis[k * 19 + j] = Wi0[half * 512 * 8 + i];
        }
        for (int i = tid; i < 512 * 6; i += 256) {
            int k = i / 6, j = i - k * 6;
            Wis[k * 19 + 8 + j] = Wi1[half * 512 * 6 + i];
        }
        for (int i = tid; i < 512 * 4; i += 256) {
            int k = i >> 2, j = i & 3;
            Wis[k * 19 + 14 + j] = Wi2[half * 512 * 4 + i];
        }
        __syncthreads();

        const float* src = half ? nxtb : curb;
        #pragma unroll 2
        for (int iter = 0; iter < 16; iter++) {
            int k = iter * 32 + lane;
            float x0 = src[(size_t)0 * FEAT + k];
            float x1 = src[(size_t)1 * FEAT + k];
            float x2 = src[(size_t)2 * FEAT + k];
            float x3 = src[(size_t)3 * FEAT + k];
            const float* wrow = &Wis[k * 19];
            #pragma unroll
            for (int j = 0; j < 18; j++) {
                float wv = wrow[j];
                acc[0][j] = fmaf(x0, wv, acc[0][j]);
                acc[1][j] = fmaf(x1, wv, acc[1][j]);
                acc[2][j] = fmaf(x2, wv, acc[2][j]);
                acc[3][j] = fmaf(x3, wv, acc[3][j]);
            }
        }
        __syncthreads();  // Wis reused next half
    }

    // reduce partial sums across the 32 lanes (butterfly)
    #pragma unroll
    for (int off = 16; off; off >>= 1) {
        #pragma unroll
        for (int r = 0; r < 4; r++)
            #pragma unroll
            for (int j = 0; j < 18; j++)
                acc[r][j] += __shfl_xor_sync(0xffffffffu, acc[r][j], off);
    }
    if (lane == 0) {
        #pragma unroll
        for (int r = 0; r < 4; r++)
            #pragma unroll
            for (int j = 0; j < 18; j++)
                logits[(w * 4 + r) * 19 + j] = acc[r][j] + bis[j];
    }
    __syncthreads();

    // softmax over the 32 agents, per column j; write final outputs
    if (tid < 18) {
        const int j = tid;
        float vals[32];
        float mx = -1e30f;
        #pragma unroll
        for (int a = 0; a < 32; a++) {
            vals[a] = logits[a * 19 + j];
            mx = fmaxf(mx, vals[a]);
        }
        float s = 0.f;
        #pragma unroll
        for (int a = 0; a < 32; a++) {
            vals[a] = expf(vals[a] - mx);
            s += vals[a];
        }
        float inv = 1.f / s;
        if (j < 8) {
            size_t base = OFF_A0 + (size_t)(frame * 32) * 8 + j;
            #pragma unroll
            for (int a = 0; a < 32; a++) out[base + (size_t)a * 8] = vals[a] * inv;
        } else if (j < 14) {
            size_t base = OFF_A1 + (size_t)(frame * 32) * 6 + (j - 8);
            #pragma unroll
            for (int a = 0; a < 32; a++) out[base + (size_t)a * 6] = vals[a] * inv;
        } else {
            size_t base = OFF_A2 + (size_t)(frame * 32) * 4 + (j - 14);
            #pragma unroll
            for (int a = 0; a < 32; a++) out[base + (size_t)a * 4] = vals[a] * inv;
        }
    }
}

// ---------------------------------------------------------------------------
extern "C" void kernel_launch(void* const* d_in, const int* in_sizes, int n_in,
                              void* d_out, int out_size)
{
    const float* cur  = (const float*)d_in[0];
    const float* nxt  = (const float*)d_in[1];
    const int*   acts = (const int*)  d_in[2];
    const float* W1   = (const float*)d_in[3];
    const float* b1   = (const float*)d_in[4];
    const float* W2   = (const float*)d_in[5];
    const float* b2   = (const float*)d_in[6];
    const float* Wi0  = (const float*)d_in[7];
    const float* bi0  = (const float*)d_in[8];
    const float* Wi1  = (const float*)d_in[9];
    const float* bi1  = (const float*)d_in[10];
    const float* Wi2  = (const float*)d_in[11];
    const float* bi2  = (const float*)d_in[12];
    float* out = (float*)d_out;

    fwd1_kernel<<<N_ROWS / 64, dim3(20, 8)>>>(cur, acts, W1, b1);
    fwd2_kernel<<<dim3(N_ROWS / 128, OUT2 / 64), dim3(8, 16)>>>(W2, b2, out);
    inv_kernel<<<N_FRAMES, 256>>>(cur, nxt, Wi0, bi0, Wi1, bi1, Wi2, bi2, out);
}

// round 2
// speedup vs baseline: 1.0013x; 1.0013x over previous
#include <cuda_runtime.h>
#include <math.h>

#define N_FRAMES 2048
#define N_AGENTS 32
#define N_ROWS (N_FRAMES * N_AGENTS)   // 65536
#define FEAT 512
#define HID 140
#define OUT2 256

// output layout: pred [65536,256] | a0 [65536,8] | a1 [65536,6] | a2 [65536,4]
#define OFF_A0 (N_ROWS * OUT2)            // 16777216
#define OFF_A1 (OFF_A0 + N_ROWS * 8)      // 17301504
#define OFF_A2 (OFF_A1 + N_ROWS * 6)      // 17694720

// scratch for hidden activations (36.7 MB), static device global (no alloc)
__device__ float g_hid[(size_t)N_ROWS * HID];

// ---------------------------------------------------------------------------
// Kernel 1: hid[M,140] = cur[M,512] @ W1[0:512,:] + onehot @ W1[512:530,:] + b1
// Block tile: BM=64, BN=140 (full), BK=32. Threads (20,8)=160. Thread tile 8x7.
// ---------------------------------------------------------------------------
__global__ __launch_bounds__(160) void fwd1_kernel(
    const float* __restrict__ cur, const int* __restrict__ actions,
    const float* __restrict__ W1, const float* __restrict__ b1)
{
    __shared__ float As[32][65];    // [k][row], padded
    __shared__ float Bs[32][140];   // [k][col]

    const int tx = threadIdx.x;     // 0..19  -> col group (7 cols)
    const int ty = threadIdx.y;     // 0..7   -> row group (8 rows)
    const int tid = ty * 20 + tx;
    const int row0 = blockIdx.x * 64;

    float acc[8][7];
    #pragma unroll
    for (int m = 0; m < 8; m++)
        #pragma unroll
        for (int n = 0; n < 7; n++) acc[m][n] = 0.f;

    for (int kb = 0; kb < 16; kb++) {
        // stage A tile: 64 rows x 32 k (coalesced along k)
        #pragma unroll
        for (int i = tid; i < 64 * 32; i += 160) {
            int r = i >> 5, k = i & 31;
            As[k][r] = cur[(size_t)(row0 + r) * FEAT + kb * 32 + k];
        }
        // stage B tile: 32 k x 140 cols (coalesced along n)
        #pragma unroll
        for (int i = tid; i < 32 * 140; i += 160) {
            int k = i / 140, n = i - k * 140;
            Bs[k][n] = W1[(size_t)(kb * 32 + k) * HID + n];
        }
        __syncthreads();

        #pragma unroll
        for (int k = 0; k < 32; k++) {
            float a[8], b[7];
            #pragma unroll
            for (int m = 0; m < 8; m++) a[m] = As[k][ty * 8 + m];
            #pragma unroll
            for (int n = 0; n < 7; n++) b[n] = Bs[k][tx * 7 + n];
            #pragma unroll
            for (int m = 0; m < 8; m++)
                #pragma unroll
                for (int n = 0; n < 7; n++)
                    acc[m][n] = fmaf(a[m], b[n], acc[m][n]);
        }
        __syncthreads();
    }

    // epilogue: + b1 + 3 one-hot rows of W1 (actions always in [0,4))
    #pragma unroll
    for (int m = 0; m < 8; m++) {
        int row = row0 + ty * 8 + m;
        int f = row >> 5, ag = row & 31;
        int i0 = actions[(f * 3 + 0) * N_AGENTS + ag];
        int i1 = actions[(f * 3 + 1) * N_AGENTS + ag];
        int i2 = actions[(f * 3 + 2) * N_AGENTS + ag];
        const float* w0 = W1 + (size_t)(FEAT + i0) * HID;
        const float* w1 = W1 + (size_t)(FEAT + 8 + i1) * HID;
        const float* w2 = W1 + (size_t)(FEAT + 14 + i2) * HID;
        #pragma unroll
        for (int n = 0; n < 7; n++) {
            int col = tx * 7 + n;
            g_hid[(size_t)row * HID + col] =
                acc[m][n] + b1[col] + w0[col] + w1[col] + w2[col];
        }
    }
}

// ---------------------------------------------------------------------------
// Kernel 2: pred[M,256] = hid[M,140] @ W2[140,256] + b2
// Block tile: BM=128, BN=64, BK=20 (140 = 7*20). Threads (8,16)=128. TT 8x8.
// ---------------------------------------------------------------------------
__global__ __launch_bounds__(128) void fwd2_kernel(
    const float* __restrict__ W2, const float* __restrict__ b2,
    float* __restrict__ out)
{
    __shared__ float As[20][129];   // [k][row], padded
    __shared__ float Bs[20][64];    // [k][col]

    const int tx = threadIdx.x;     // 0..7  -> col group (8 cols)
    const int ty = threadIdx.y;     // 0..15 -> row group (8 rows)
    const int tid = ty * 8 + tx;
    const int row0 = blockIdx.x * 128;
    const int col0 = blockIdx.y * 64;

    float acc[8][8];
    #pragma unroll
    for (int m = 0; m < 8; m++)
        #pragma unroll
        for (int n = 0; n < 8; n++) acc[m][n] = 0.f;

    for (int kb = 0; kb < 7; kb++) {
        #pragma unroll
        for (int i = tid; i < 128 * 20; i += 128) {
            int r = i / 20, k = i - r * 20;
            As[k][r] = g_hid[(size_t)(row0 + r) * HID + kb * 20 + k];
        }
        #pragma unroll
        for (int i = tid; i < 20 * 64; i += 128) {
            int k = i >> 6, n = i & 63;
            Bs[k][n] = W2[(size_t)(kb * 20 + k) * OUT2 + col0 + n];
        }
        __syncthreads();

        #pragma unroll
        for (int k = 0; k < 20; k++) {
            float a[8], b[8];
            #pragma unroll
            for (int m = 0; m < 8; m++) a[m] = As[k][ty * 8 + m];
            #pragma unroll
            for (int n = 0; n < 8; n++) b[n] = Bs[k][tx * 8 + n];
            #pragma unroll
            for (int m = 0; m < 8; m++)
                #pragma unroll
                for (int n = 0; n < 8; n++)
                    acc[m][n] = fmaf(a[m], b[n], acc[m][n]);
        }
        __syncthreads();
    }

    #pragma unroll
    for (int m = 0; m < 8; m++) {
        int row = row0 + ty * 8 + m;
        #pragma unroll
        for (int n = 0; n < 8; n++) {
            int col = col0 + tx * 8 + n;
            out[(size_t)row * OUT2 + col] = acc[m][n] + b2[col];
        }
    }
}

// ---------------------------------------------------------------------------
// Kernel 3: inverse dynamics + softmax over the AGENT axis.
// logits[row, 0:18] = [cur|next](row) @ [Wi0|Wi1|Wi2] + [bi0|bi1|bi2]
// softmax is over the 32 agents of each frame, per column, per group.
// One block per frame (32 rows). 8 warps x 4 rows/warp, K split over lanes.
// Wi staged to static smem in two K-halves (half0 = cur, half1 = next).
// ---------------------------------------------------------------------------
__global__ __launch_bounds__(256) void inv_kernel(
    const float* __restrict__ cur, const float* __restrict__ nxt,
    const float* __restrict__ Wi0, const float* __restrict__ bi0,
    const float* __restrict__ Wi1, const float* __restrict__ bi1,
    const float* __restrict__ Wi2, const float* __restrict__ bi2,
    float* __restrict__ out)
{
    __shared__ float Wis[512 * 19];   // [k][j], padded stride 19 (coprime w/ 32)
    __shared__ float logits[32 * 19]; // [agent][j]
    __shared__ float bis[18];

    const int tid = threadIdx.x;
    const int frame = blockIdx.x;
    const int w = tid >> 5, lane = tid & 31;
    const int rbase = frame * N_AGENTS + w * 4;

    if (tid < 8)       bis[tid] = bi0[tid];
    else if (tid < 14) bis[tid] = bi1[tid - 8];
    else if (tid < 18) bis[tid] = bi2[tid - 14];

    float acc[4][18];
    #pragma unroll
    for (int r = 0; r < 4; r++)
        #pragma unroll
        for (int j = 0; j < 18; j++) acc[r][j] = 0.f;

    const float* curb = cur + (size_t)rbase * FEAT;
    const float* nxtb = nxt + (size_t)rbase * FEAT;

    for (int half = 0; half < 2; half++) {
        // stage this K-half of the combined inverse weight matrix
        for (int i = tid; i < 512 * 8; i += 256) {
            int k = i >> 3, j = i & 7;
            Wis[k * 19 + j] = Wi0[half * 512 * 8 + i];
        }
        for (int i = tid; i < 512 * 6; i += 256) {
            int k = i / 6, j = i - k * 6;
            Wis[k * 19 + 8 + j] = Wi1[half * 512 * 6 + i];
        }
        for (int i = tid; i < 512 * 4; i += 256) {
            int k = i >> 2, j = i & 3;
            Wis[k * 19 + 14 + j] = Wi2[half * 512 * 4 + i];
        }
        __syncthreads();

        const float* src = half ? nxtb : curb;
        #pragma unroll 2
        for (int iter = 0; iter < 16; iter++) {
            int k = iter * 32 + lane;
            float x0 = src[(size_t)0 * FEAT + k];
            float x1 = src[(size_t)1 * FEAT + k];
            float x2 = src[(size_t)2 * FEAT + k];
            float x3 = src[(size_t)3 * FEAT + k];
            const float* wrow = &Wis[k * 19];
            #pragma unroll
            for (int j = 0; j < 18; j++) {
                float wv = wrow[j];
                acc[0][j] = fmaf(x0, wv, acc[0][j]);
                acc[1][j] = fmaf(x1, wv, acc[1][j]);
                acc[2][j] = fmaf(x2, wv, acc[2][j]);
                acc[3][j] = fmaf(x3, wv, acc[3][j]);
            }
        }
        __syncthreads();  // Wis reused next half
    }

    // reduce partial sums across the 32 lanes (butterfly)
    #pragma unroll
    for (int off = 16; off; off >>= 1) {
        #pragma unroll
        for (int r = 0; r < 4; r++)
            #pragma unroll
            for (int j = 0; j < 18; j++)
                acc[r][j] += __shfl_xor_sync(0xffffffffu, acc[r][j], off);
    }
    if (lane == 0) {
        #pragma unroll
        for (int r = 0; r < 4; r++)
            #pragma unroll
            for (int j = 0; j < 18; j++)
                logits[(w * 4 + r) * 19 + j] = acc[r][j] + bis[j];
    }
    __syncthreads();

    // softmax over the 32 agents, per column j; write final outputs
    if (tid < 18) {
        const int j = tid;
        float vals[32];
        float mx = -1e30f;
        #pragma unroll
        for (int a = 0; a < 32; a++) {
            vals[a] = logits[a * 19 + j];
            mx = fmaxf(mx, vals[a]);
        }
        float s = 0.f;
        #pragma unroll
        for (int a = 0; a < 32; a++) {
            vals[a] = expf(vals[a] - mx);
            s += vals[a];
        }
        float inv = 1.f / s;
        if (j < 8) {
            size_t base = OFF_A0 + (size_t)(frame * 32) * 8 + j;
            #pragma unroll
            for (int a = 0; a < 32; a++) out[base + (size_t)a * 8] = vals[a] * inv;
        } else if (j < 14) {
            size_t base = OFF_A1 + (size_t)(frame * 32) * 6 + (j - 8);
            #pragma unroll
            for (int a = 0; a < 32; a++) out[base + (size_t)a * 6] = vals[a] * inv;
        } else {
            size_t base = OFF_A2 + (size_t)(frame * 32) * 4 + (j - 14);
            #pragma unroll
            for (int a = 0; a < 32; a++) out[base + (size_t)a * 4] = vals[a] * inv;
        }
    }
}

// ---------------------------------------------------------------------------
extern "C" void kernel_launch(void* const* d_in, const int* in_sizes, int n_in,
                              void* d_out, int out_size)
{
    const float* cur  = (const float*)d_in[0];
    const float* nxt  = (const float*)d_in[1];
    const int*   acts = (const int*)  d_in[2];
    const float* W1   = (const float*)d_in[3];
    const float* b1   = (const float*)d_in[4];
    const float* W2   = (const float*)d_in[5];
    const float* b2   = (const float*)d_in[6];
    const float* Wi0  = (const float*)d_in[7];
    const float* bi0  = (const float*)d_in[8];
    const float* Wi1  = (const float*)d_in[9];
    const float* bi1  = (const float*)d_in[10];
    const float* Wi2  = (const float*)d_in[11];
    const float* bi2  = (const float*)d_in[12];
    float* out = (float*)d_out;

    fwd1_kernel<<<N_ROWS / 64, dim3(20, 8)>>>(cur, acts, W1, b1);
    fwd2_kernel<<<dim3(N_ROWS / 128, OUT2 / 64), dim3(8, 16)>>>(W2, b2, out);
    inv_kernel<<<N_FRAMES, 256>>>(cur, nxt, Wi0, bi0, Wi1, bi1, Wi2, bi2, out);
}

// round 3
// speedup vs baseline: 6.6163x; 6.6080x over previous
#include <cuda_runtime.h>
#include <cuda_bf16.h>
#include <stdint.h>
#include <math.h>

#define N_FRAMES 2048
#define N_AGENTS 32
#define N_ROWS 65536
#define FEAT 512
#define HID 140
#define OUT2 256

#define OFF_A0 (N_ROWS * OUT2)
#define OFF_A1 (OFF_A0 + N_ROWS * 8)
#define OFF_A2 (OFF_A1 + N_ROWS * 6)

// padded GEMM dims
#define K1P 544   // 512 feat + 18 onehot + bias(530) + pad
#define N1P 144   // 140 hid + ones-col(140) + pad
#define K2P 144
#define KIP 1024  // cur|next
#define NIP 24

// pre-split transposed weights + hidden scratch (static device globals)
__device__ __align__(16) __nv_bfloat16 g_w1t_hi[N1P * K1P];
__device__ __align__(16) __nv_bfloat16 g_w1t_lo[N1P * K1P];
__device__ __align__(16) __nv_bfloat16 g_w2t_hi[OUT2 * K2P];
__device__ __align__(16) __nv_bfloat16 g_w2t_lo[OUT2 * K2P];
__device__ __align__(16) __nv_bfloat16 g_wit_hi[NIP * KIP];
__device__ __align__(16) __nv_bfloat16 g_wit_lo[NIP * KIP];
__device__ __align__(16) __nv_bfloat16 g_hid_hi[(size_t)N_ROWS * N1P];
__device__ __align__(16) __nv_bfloat16 g_hid_lo[(size_t)N_ROWS * N1P];

// ---------------------------------------------------------------- helpers
__device__ __forceinline__ uint32_t smaddr(const void* p) {
    return (uint32_t)__cvta_generic_to_shared(p);
}
__device__ __forceinline__ void ldsm_x4(uint32_t* r, uint32_t a) {
    asm volatile("ldmatrix.sync.aligned.m8n8.x4.shared.b16 {%0,%1,%2,%3}, [%4];"
        : "=r"(r[0]), "=r"(r[1]), "=r"(r[2]), "=r"(r[3]) : "r"(a));
}
__device__ __forceinline__ void ldsm_x2(uint32_t* r, uint32_t a) {
    asm volatile("ldmatrix.sync.aligned.m8n8.x2.shared.b16 {%0,%1}, [%2];"
        : "=r"(r[0]), "=r"(r[1]) : "r"(a));
}
__device__ __forceinline__ void mma_bf16(float* d, const uint32_t* a, const uint32_t* b) {
    asm volatile("mma.sync.aligned.m16n8k16.row.col.f32.bf16.bf16.f32 "
        "{%0,%1,%2,%3}, {%4,%5,%6,%7}, {%8,%9}, {%0,%1,%2,%3};"
        : "+f"(d[0]), "+f"(d[1]), "+f"(d[2]), "+f"(d[3])
        : "r"(a[0]), "r"(a[1]), "r"(a[2]), "r"(a[3]), "r"(b[0]), "r"(b[1]));
}
__device__ __forceinline__ uint32_t pack2(__nv_bfloat16 a, __nv_bfloat16 b) {
    __nv_bfloat162 t; t.x = a; t.y = b;
    return *reinterpret_cast<uint32_t*>(&t);
}
__device__ __forceinline__ void split1(float v, __nv_bfloat16& hi, __nv_bfloat16& lo) {
    hi = __float2bfloat16_rn(v);
    lo = __float2bfloat16_rn(v - __bfloat162float(hi));
}

// ---------------------------------------------------------------- prep
__global__ void prep_kernel(
    const float* __restrict__ W1, const float* __restrict__ b1,
    const float* __restrict__ W2, const float* __restrict__ b2,
    const float* __restrict__ Wi0, const float* __restrict__ Wi1,
    const float* __restrict__ Wi2)
{
    int idx = blockIdx.x * 256 + threadIdx.x;
    if (idx < N1P * K1P) {
        int n = idx / K1P, k = idx - n * K1P;
        float v = 0.f;
        if (n < HID) {
            if (k < 530)       v = W1[(size_t)k * HID + n];
            else if (k == 530) v = b1[n];
        }
        split1(v, g_w1t_hi[idx], g_w1t_lo[idx]);
    }
    if (idx < OUT2 * K2P) {
        int n = idx / K2P, k = idx - n * K2P;
        float v = 0.f;
        if (k < HID)       v = W2[(size_t)k * OUT2 + n];
        else if (k == HID) v = b2[n];
        split1(v, g_w2t_hi[idx], g_w2t_lo[idx]);
    }
    if (idx < NIP * KIP) {
        int n = idx / KIP, k = idx - n * KIP;
        float v = 0.f;
        if (n < 8)        v = Wi0[(size_t)k * 8 + n];
        else if (n < 14)  v = Wi1[(size_t)k * 6 + (n - 8)];
        else if (n < 18)  v = Wi2[(size_t)k * 4 + (n - 14)];
        split1(v, g_wit_hi[idx], g_wit_lo[idx]);
    }
}

// stage a 128x64 fp32 feature chunk -> split bf16 smem tiles (stride 72)
__device__ __forceinline__ void stage_feat(
    __nv_bfloat16* sA_hi, __nv_bfloat16* sA_lo,
    const float* __restrict__ src, int row0, int c0, int tid)
{
    #pragma unroll
    for (int j = 0; j < 8; j++) {
        int i = tid + j * 256;
        int r = i >> 4, c4 = (i & 15) << 2;
        float4 v = *(const float4*)(src + (size_t)(row0 + r) * FEAT + c0 + c4);
        __nv_bfloat16 h0, h1, h2, h3, l0, l1, l2, l3;
        split1(v.x, h0, l0); split1(v.y, h1, l1);
        split1(v.z, h2, l2); split1(v.w, h3, l3);
        *(uint2*)(sA_hi + r * 72 + c4) = make_uint2(pack2(h0, h1), pack2(h2, h3));
        *(uint2*)(sA_lo + r * 72 + c4) = make_uint2(pack2(l0, l1), pack2(l2, l3));
    }
}

// ---------------------------------------------------------------- GEMM1
// hid[65536,144] = [cur | onehot | 1] @ W1aug   (dyn smem 78336B)
__global__ __launch_bounds__(256, 2) void gemm1_kernel(
    const float* __restrict__ cur, const int* __restrict__ actions)
{
    extern __shared__ char smem[];
    __nv_bfloat16* sA_hi = (__nv_bfloat16*)(smem);           // 128*72
    __nv_bfloat16* sA_lo = (__nv_bfloat16*)(smem + 18432);
    __nv_bfloat16* sB_hi = (__nv_bfloat16*)(smem + 36864);   // 144*72
    __nv_bfloat16* sB_lo = (__nv_bfloat16*)(smem + 57600);

    const int tid = threadIdx.x, lane = tid & 31, w = tid >> 5;
    const int row0 = blockIdx.x * 128;
    const int m0 = (w >> 1) * 32, n0 = (w & 1) * 72;

    float acc[2][9][4];
    #pragma unroll
    for (int a = 0; a < 2; a++)
        #pragma unroll
        for (int b = 0; b < 9; b++)
            #pragma unroll
            for (int c = 0; c < 4; c++) acc[a][b][c] = 0.f;

    for (int kb = 0; kb < 9; kb++) {
        if (kb < 8) {
            stage_feat(sA_hi, sA_lo, cur, row0, kb * 64, tid);
        } else {
            #pragma unroll
            for (int j = 0; j < 8; j++) {
                int i = tid + j * 256;
                int r = i >> 4, c4 = (i & 15) << 2;
                *(uint2*)(sA_hi + r * 72 + c4) = make_uint2(0u, 0u);
                *(uint2*)(sA_lo + r * 72 + c4) = make_uint2(0u, 0u);
            }
            __syncthreads();
            if (tid < 128) {
                int r = tid;
                int f = (row0 + r) >> 5, ag = (row0 + r) & 31;
                int i0 = actions[(f * 3 + 0) * N_AGENTS + ag];
                int i1 = actions[(f * 3 + 1) * N_AGENTS + ag];
                int i2 = actions[(f * 3 + 2) * N_AGENTS + ag];
                __nv_bfloat16 one = __float2bfloat16_rn(1.f);
                sA_hi[r * 72 + i0] = one;
                sA_hi[r * 72 + 8 + i1] = one;
                sA_hi[r * 72 + 14 + i2] = one;
                sA_hi[r * 72 + 18] = one;      // bias column (k=530)
            }
        }
        {
            int kb64 = kb * 64;
            #pragma unroll
            for (int j = 0; j < 9; j++) {
                int i = tid + j * 256;          // 144*16 = 2304
                int n = i >> 4, c4 = (i & 15) << 2;
                *(uint2*)(sB_hi + n * 72 + c4) = *(const uint2*)(g_w1t_hi + n * K1P + kb64 + c4);
                *(uint2*)(sB_lo + n * 72 + c4) = *(const uint2*)(g_w1t_lo + n * K1P + kb64 + c4);
            }
        }
        __syncthreads();

        #pragma unroll
        for (int ks = 0; ks < 4; ks++) {
            int k0 = ks * 16;
            uint32_t ah[2][4], al[2][4];
            #pragma unroll
            for (int mt = 0; mt < 2; mt++) {
                int r = m0 + mt * 16 + (lane & 15);
                int c = k0 + ((lane >> 4) << 3);
                ldsm_x4(ah[mt], smaddr(sA_hi + r * 72 + c));
                ldsm_x4(al[mt], smaddr(sA_lo + r * 72 + c));
            }
            #pragma unroll
            for (int nt = 0; nt < 9; nt++) {
                uint32_t bh[2], bl[2];
                int l15 = lane & 15;
                int nr = n0 + nt * 8 + (l15 & 7);
                int c = k0 + ((l15 >> 3) << 3);
                ldsm_x2(bh, smaddr(sB_hi + nr * 72 + c));
                ldsm_x2(bl, smaddr(sB_lo + nr * 72 + c));
                #pragma unroll
                for (int mt = 0; mt < 2; mt++) {
                    mma_bf16(acc[mt][nt], ah[mt], bh);
                    mma_bf16(acc[mt][nt], ah[mt], bl);
                    mma_bf16(acc[mt][nt], al[mt], bh);
                }
            }
        }
        __syncthreads();
    }

    // epilogue: split-store hid (insert ones column at 140 for b2)
    #pragma unroll
    for (int mt = 0; mt < 2; mt++) {
        #pragma unroll
        for (int nt = 0; nt < 9; nt++) {
            int col = n0 + nt * 8 + ((lane & 3) << 1);
            int rb = row0 + m0 + mt * 16 + (lane >> 2);
            #pragma unroll
            for (int h = 0; h < 2; h++) {
                float v0 = acc[mt][nt][h * 2 + 0];
                float v1 = acc[mt][nt][h * 2 + 1];
                if (col == 140) v0 = 1.f;
                int row = rb + h * 8;
                __nv_bfloat16 h0, h1, l0, l1;
                split1(v0, h0, l0); split1(v1, h1, l1);
                *(uint32_t*)(g_hid_hi + (size_t)row * N1P + col) = pack2(h0, h1);
                *(uint32_t*)(g_hid_lo + (size_t)row * N1P + col) = pack2(l0, l1);
            }
        }
    }
}

// ---------------------------------------------------------------- GEMM2
// pred[65536,256] = [hid | 1] @ W2aug   (static smem 43008B)
__global__ __launch_bounds__(256) void gemm2_kernel(float* __restrict__ out)
{
    __shared__ __nv_bfloat16 sA_hi[128 * 56], sA_lo[128 * 56];
    __shared__ __nv_bfloat16 sB_hi[64 * 56],  sB_lo[64 * 56];

    const int tid = threadIdx.x, lane = tid & 31, w = tid >> 5;
    const int row0 = blockIdx.x * 128;
    const int col0 = blockIdx.y * 64;
    const int m0 = (w >> 1) * 32, n0 = (w & 1) * 32;

    float acc[2][4][4];
    #pragma unroll
    for (int a = 0; a < 2; a++)
        #pragma unroll
        for (int b = 0; b < 4; b++)
            #pragma unroll
            for (int c = 0; c < 4; c++) acc[a][b][c] = 0.f;

    for (int kb = 0; kb < 3; kb++) {
        int kb48 = kb * 48;
        #pragma unroll
        for (int j = 0; j < 6; j++) {       // A: 128*12 = 1536 uint2 per matrix
            int i = tid + j * 256;
            int r = i / 12, c4 = (i - r * 12) << 2;
            *(uint2*)(sA_hi + r * 56 + c4) = *(const uint2*)(g_hid_hi + (size_t)(row0 + r) * N1P + kb48 + c4);
            *(uint2*)(sA_lo + r * 56 + c4) = *(const uint2*)(g_hid_lo + (size_t)(row0 + r) * N1P + kb48 + c4);
        }
        #pragma unroll
        for (int j = 0; j < 3; j++) {       // B: 64*12 = 768 uint2 per matrix
            int i = tid + j * 256;
            int n = i / 12, c4 = (i - n * 12) << 2;
            *(uint2*)(sB_hi + n * 56 + c4) = *(const uint2*)(g_w2t_hi + (size_t)(col0 + n) * K2P + kb48 + c4);
            *(uint2*)(sB_lo + n * 56 + c4) = *(const uint2*)(g_w2t_lo + (size_t)(col0 + n) * K2P + kb48 + c4);
        }
        __syncthreads();

        #pragma unroll
        for (int ks = 0; ks < 3; ks++) {
            int k0 = ks * 16;
            uint32_t ah[2][4], al[2][4];
            #pragma unroll
            for (int mt = 0; mt < 2; mt++) {
                int r = m0 + mt * 16 + (lane & 15);
                int c = k0 + ((lane >> 4) << 3);
                ldsm_x4(ah[mt], smaddr(sA_hi + r * 56 + c));
                ldsm_x4(al[mt], smaddr(sA_lo + r * 56 + c));
            }
            #pragma unroll
            for (int nt = 0; nt < 4; nt++) {
                uint32_t bh[2], bl[2];
                int l15 = lane & 15;
                int nr = n0 + nt * 8 + (l15 & 7);
                int c = k0 + ((l15 >> 3) << 3);
                ldsm_x2(bh, smaddr(sB_hi + nr * 56 + c));
                ldsm_x2(bl, smaddr(sB_lo + nr * 56 + c));
                #pragma unroll
                for (int mt = 0; mt < 2; mt++) {
                    mma_bf16(acc[mt][nt], ah[mt], bh);
                    mma_bf16(acc[mt][nt], ah[mt], bl);
                    mma_bf16(acc[mt][nt], al[mt], bh);
                }
            }
        }
        __syncthreads();
    }

    #pragma unroll
    for (int mt = 0; mt < 2; mt++) {
        #pragma unroll
        for (int nt = 0; nt < 4; nt++) {
            int col = col0 + n0 + nt * 8 + ((lane & 3) << 1);
            int rb = row0 + m0 + mt * 16 + (lane >> 2);
            *(float2*)(out + (size_t)rb * OUT2 + col) =
                make_float2(acc[mt][nt][0], acc[mt][nt][1]);
            *(float2*)(out + (size_t)(rb + 8) * OUT2 + col) =
                make_float2(acc[mt][nt][2], acc[mt][nt][3]);
        }
    }
}

// ---------------------------------------------------------------- INV
// logits[65536,24] = [cur|next] @ Wi_aug, then softmax over agents.
// (inverse biases omitted: constant per column over the agent axis -> cancel)
// dyn smem 148736B, 4 frames per block.
__global__ __launch_bounds__(256, 1) void inv_kernel(
    const float* __restrict__ cur, const float* __restrict__ nxt,
    float* __restrict__ out)
{
    extern __shared__ char smem[];
    __nv_bfloat16* sBI_hi = (__nv_bfloat16*)(smem);            // 24*1032
    __nv_bfloat16* sBI_lo = (__nv_bfloat16*)(smem + 49536);
    __nv_bfloat16* sA_hi  = (__nv_bfloat16*)(smem + 99072);    // 128*72
    __nv_bfloat16* sA_lo  = (__nv_bfloat16*)(smem + 117504);
    float*         sL     = (float*)        (smem + 135936);   // 128*25

    const int tid = threadIdx.x, lane = tid & 31, w = tid >> 5;
    const int row0 = blockIdx.x * 128;
    const int m0 = w * 16;

    // stage full inverse weight matrix once (24 x 1024, stride 1032)
    #pragma unroll
    for (int j = 0; j < 24; j++) {
        int i = tid + j * 256;              // 24*256 = 6144 uint2 per matrix
        int n = i >> 8, c4 = (i & 255) << 2;
        *(uint2*)(sBI_hi + n * 1032 + c4) = *(const uint2*)(g_wit_hi + n * KIP + c4);
        *(uint2*)(sBI_lo + n * 1032 + c4) = *(const uint2*)(g_wit_lo + n * KIP + c4);
    }

    float acc[3][4];
    #pragma unroll
    for (int b = 0; b < 3; b++)
        #pragma unroll
        for (int c = 0; c < 4; c++) acc[b][c] = 0.f;

    for (int kb = 0; kb < 16; kb++) {
        __syncthreads();
        if (kb < 8) stage_feat(sA_hi, sA_lo, cur, row0, kb * 64, tid);
        else        stage_feat(sA_hi, sA_lo, nxt, row0, (kb - 8) * 64, tid);
        __syncthreads();

        #pragma unroll
        for (int ks = 0; ks < 4; ks++) {
            int k0 = ks * 16;
            uint32_t ah[4], al[4];
            {
                int r = m0 + (lane & 15);
                int c = k0 + ((lane >> 4) << 3);
                ldsm_x4(ah, smaddr(sA_hi + r * 72 + c));
                ldsm_x4(al, smaddr(sA_lo + r * 72 + c));
            }
            int kg = kb * 64 + k0;
            #pragma unroll
            for (int nt = 0; nt < 3; nt++) {
                uint32_t bh[2], bl[2];
                int l15 = lane & 15;
                int nr = nt * 8 + (l15 & 7);
                int c = kg + ((l15 >> 3) << 3);
                ldsm_x2(bh, smaddr(sBI_hi + nr * 1032 + c));
                ldsm_x2(bl, smaddr(sBI_lo + nr * 1032 + c));
                mma_bf16(acc[nt], ah, bh);
                mma_bf16(acc[nt], ah, bl);
                mma_bf16(acc[nt], al, bh);
            }
        }
    }

    // logits -> smem
    #pragma unroll
    for (int nt = 0; nt < 3; nt++) {
        int col = nt * 8 + ((lane & 3) << 1);
        int rl = m0 + (lane >> 2);
        sL[rl * 25 + col]           = acc[nt][0];
        sL[rl * 25 + col + 1]       = acc[nt][1];
        sL[(rl + 8) * 25 + col]     = acc[nt][2];
        sL[(rl + 8) * 25 + col + 1] = acc[nt][3];
    }
    __syncthreads();

    // softmax over the 32 agents of each of the 4 frames
    if (tid < 72) {
        int f = tid / 18, j = tid - f * 18;
        float vals[32], mx = -1e30f;
        #pragma unroll
        for (int a = 0; a < 32; a++) {
            vals[a] = sL[(f * 32 + a) * 25 + j];
            mx = fmaxf(mx, vals[a]);
        }
        float s = 0.f;
        #pragma unroll
        for (int a = 0; a < 32; a++) { vals[a] = expf(vals[a] - mx); s += vals[a]; }
        float inv = 1.f / s;
        int frame = blockIdx.x * 4 + f;
        if (j < 8) {
            size_t base = OFF_A0 + (size_t)(frame * 32) * 8 + j;
            #pragma unroll
            for (int a = 0; a < 32; a++) out[base + (size_t)a * 8] = vals[a] * inv;
        } else if (j < 14) {
            size_t base = OFF_A1 + (size_t)(frame * 32) * 6 + (j - 8);
            #pragma unroll
            for (int a = 0; a < 32; a++) out[base + (size_t)a * 6] = vals[a] * inv;
        } else {
            size_t base = OFF_A2 + (size_t)(frame * 32) * 4 + (j - 14);
            #pragma unroll
            for (int a = 0; a < 32; a++) out[base + (size_t)a * 4] = vals[a] * inv;
        }
    }
}

// ----------------------------------------------------------------
extern "C" void kernel_launch(void* const* d_in, const int* in_sizes, int n_in,
                              void* d_out, int out_size)
{
    const float* cur  = (const float*)d_in[0];
    const float* nxt  = (const float*)d_in[1];
    const int*   acts = (const int*)  d_in[2];
    const float* W1   = (const float*)d_in[3];
    const float* b1   = (const float*)d_in[4];
    const float* W2   = (const float*)d_in[5];
    const float* b2   = (const float*)d_in[6];
    const float* Wi0  = (const float*)d_in[7];
    const float* Wi1  = (const float*)d_in[9];
    const float* Wi2  = (const float*)d_in[11];
    float* out = (float*)d_out;

    cudaFuncSetAttribute(gemm1_kernel, cudaFuncAttributeMaxDynamicSharedMemorySize, 78336);
    cudaFuncSetAttribute(inv_kernel,   cudaFuncAttributeMaxDynamicSharedMemorySize, 148736);

    prep_kernel<<<(N1P * K1P + 255) / 256, 256>>>(W1, b1, W2, b2, Wi0, Wi1, Wi2);
    gemm1_kernel<<<N_ROWS / 128, 256, 78336>>>(cur, acts);
    gemm2_kernel<<<dim3(N_ROWS / 128, OUT2 / 64), 256>>>(out);
    inv_kernel<<<N_ROWS / 128, 256, 148736>>>(cur, nxt, out);
}

// round 4
// speedup vs baseline: 10.0458x; 1.5183x over previous
#include <cuda_runtime.h>
#include <cuda_fp16.h>
#include <stdint.h>
#include <math.h>

#define N_FRAMES 2048
#define N_AGENTS 32
#define N_ROWS 65536
#define FEAT 512
#define HID 140
#define OUT2 256

#define OFF_A0 (N_ROWS * OUT2)
#define OFF_A1 (OFF_A0 + N_ROWS * 8)
#define OFF_A2 (OFF_A1 + N_ROWS * 6)

// padded dims
#define K1P 576   // 512 feat + 64 special (18 onehot + bias@530 + pad)
#define N1P 144   // 140 hid + ones@140 + pad
#define K2P 144
#define KIP 1024  // cur|next
#define NIP 24

// weights: split fp16 (hi/lo) on the B side; hid scratch: single fp16
__device__ __align__(16) __half g_w1t_hi[N1P * K1P];
__device__ __align__(16) __half g_w1t_lo[N1P * K1P];
__device__ __align__(16) __half g_w2t_hi[OUT2 * K2P];
__device__ __align__(16) __half g_w2t_lo[OUT2 * K2P];
__device__ __align__(16) __half g_wit_hi[NIP * KIP];
__device__ __align__(16) __half g_wit_lo[NIP * KIP];
__device__ __align__(16) __half g_hid[(size_t)N_ROWS * N1P];

// ---------------------------------------------------------------- helpers
__device__ __forceinline__ uint32_t smaddr(const void* p) {
    return (uint32_t)__cvta_generic_to_shared(p);
}
__device__ __forceinline__ void ldsm_x4(uint32_t* r, uint32_t a) {
    asm volatile("ldmatrix.sync.aligned.m8n8.x4.shared.b16 {%0,%1,%2,%3}, [%4];"
        : "=r"(r[0]), "=r"(r[1]), "=r"(r[2]), "=r"(r[3]) : "r"(a));
}
__device__ __forceinline__ void ldsm_x2(uint32_t* r, uint32_t a) {
    asm volatile("ldmatrix.sync.aligned.m8n8.x2.shared.b16 {%0,%1}, [%2];"
        : "=r"(r[0]), "=r"(r[1]) : "r"(a));
}
__device__ __forceinline__ void mma_f16(float* d, const uint32_t* a, const uint32_t* b) {
    asm volatile("mma.sync.aligned.m16n8k16.row.col.f32.f16.f16.f32 "
        "{%0,%1,%2,%3}, {%4,%5,%6,%7}, {%8,%9}, {%0,%1,%2,%3};"
        : "+f"(d[0]), "+f"(d[1]), "+f"(d[2]), "+f"(d[3])
        : "r"(a[0]), "r"(a[1]), "r"(a[2]), "r"(a[3]), "r"(b[0]), "r"(b[1]));
}
__device__ __forceinline__ uint32_t pack2h(__half a, __half b) {
    __half2 t; t.x = a; t.y = b;
    return *reinterpret_cast<uint32_t*>(&t);
}
__device__ __forceinline__ void split1h(float v, __half& hi, __half& lo) {
    hi = __float2half_rn(v);
    lo = __float2half_rn(v - __half2float(hi));
}

// ---------------------------------------------------------------- prep
__global__ void prep_kernel(
    const float* __restrict__ W1, const float* __restrict__ b1,
    const float* __restrict__ W2, const float* __restrict__ b2,
    const float* __restrict__ Wi0, const float* __restrict__ Wi1,
    const float* __restrict__ Wi2)
{
    int idx = blockIdx.x * 256 + threadIdx.x;
    if (idx < N1P * K1P) {
        int n = idx / K1P, k = idx - n * K1P;
        float v = 0.f;
        if (n < HID) {
            if (k < 530)       v = W1[(size_t)k * HID + n];
            else if (k == 530) v = b1[n];
        }
        split1h(v, g_w1t_hi[idx], g_w1t_lo[idx]);
    }
    if (idx < OUT2 * K2P) {
        int n = idx / K2P, k = idx - n * K2P;
        float v = 0.f;
        if (k < HID)       v = W2[(size_t)k * OUT2 + n];
        else if (k == HID) v = b2[n];
        split1h(v, g_w2t_hi[idx], g_w2t_lo[idx]);
    }
    if (idx < NIP * KIP) {
        int n = idx / KIP, k = idx - n * KIP;
        float v = 0.f;
        if (n < 8)        v = Wi0[(size_t)k * 8 + n];
        else if (n < 14)  v = Wi1[(size_t)k * 6 + (n - 8)];
        else if (n < 18)  v = Wi2[(size_t)k * 4 + (n - 14)];
        split1h(v, g_wit_hi[idx], g_wit_lo[idx]);
    }
}

// stage a 128x64 fp32 chunk -> single fp16 smem (stride 72)
__device__ __forceinline__ void stage_feat(
    __half* sA, const float* __restrict__ src, int row0, int c0, int tid)
{
    #pragma unroll
    for (int j = 0; j < 8; j++) {
        int i = tid + j * 256;
        int r = i >> 4, c4 = (i & 15) << 2;
        float4 v = *(const float4*)(src + (size_t)(row0 + r) * FEAT + c0 + c4);
        uint2 u;
        u.x = pack2h(__float2half_rn(v.x), __float2half_rn(v.y));
        u.y = pack2h(__float2half_rn(v.z), __float2half_rn(v.w));
        *(uint2*)(sA + r * 72 + c4) = u;
    }
}

// ---------------------------------------------------------------- FUSED
// gemm1 (hid = [cur|onehot|1] @ W1aug) + inv (logits = [cur|nxt] @ Wi) +
// agent-axis softmax. Shares cur A-tiles between the two GEMMs.
// dyn smem 79616 B -> 2 CTAs/SM.
__global__ __launch_bounds__(256, 2) void fused1_kernel(
    const float* __restrict__ cur, const float* __restrict__ nxt,
    const int* __restrict__ actions, float* __restrict__ out)
{
    extern __shared__ char smem[];
    __half* sA     = (__half*)(smem);            // 128*72
    __half* sB_hi  = (__half*)(smem + 18432);    // 144*72
    __half* sB_lo  = (__half*)(smem + 39168);
    __half* sWi_hi = (__half*)(smem + 59904);    // 24*72
    __half* sWi_lo = (__half*)(smem + 63360);
    float*  sL     = (float*) (smem + 66816);    // 128*25

    const int tid = threadIdx.x, lane = tid & 31, w = tid >> 5;
    const int row0 = blockIdx.x * 128;
    const int m0 = (w >> 1) * 32, n0 = (w & 1) * 72;   // gemm1 warp tile
    const int mI = w * 16;                              // inv warp rows

    float acc1[2][9][4];
    #pragma unroll
    for (int a = 0; a < 2; a++)
        #pragma unroll
        for (int b = 0; b < 9; b++)
            #pragma unroll
            for (int c = 0; c < 4; c++) acc1[a][b][c] = 0.f;
    float accI[3][4];
    #pragma unroll
    for (int b = 0; b < 3; b++)
        #pragma unroll
        for (int c = 0; c < 4; c++) accI[b][c] = 0.f;

    for (int kb = 0; kb < 17; kb++) {
        if (kb) __syncthreads();
        const bool g1 = (kb < 8) || (kb == 16);
        const bool iv = (kb < 16);

        // ---- stage A
        if (kb < 8) {
            stage_feat(sA, cur, row0, kb * 64, tid);
        } else if (kb < 16) {
            stage_feat(sA, nxt, row0, (kb - 8) * 64, tid);
        } else {
            #pragma unroll
            for (int j = 0; j < 8; j++) {
                int i = tid + j * 256;
                int r = i >> 4, c4 = (i & 15) << 2;
                *(uint2*)(sA + r * 72 + c4) = make_uint2(0u, 0u);
            }
            __syncthreads();
            if (tid < 128) {
                int r = tid;
                int f = (row0 + r) >> 5, ag = (row0 + r) & 31;
                int i0 = actions[(f * 3 + 0) * N_AGENTS + ag];
                int i1 = actions[(f * 3 + 1) * N_AGENTS + ag];
                int i2 = actions[(f * 3 + 2) * N_AGENTS + ag];
                __half one = __float2half_rn(1.f);
                sA[r * 72 + i0] = one;
                sA[r * 72 + 8 + i1] = one;
                sA[r * 72 + 14 + i2] = one;
                sA[r * 72 + 18] = one;             // b1 column (k=530)
            }
        }
        // ---- stage B1 chunk (W1^T)
        if (g1) {
            int kb64 = (kb < 8) ? kb * 64 : 512;
            #pragma unroll
            for (int j = 0; j < 9; j++) {
                int i = tid + j * 256;              // 144*16 = 2304 uint2
                int n = i >> 4, c4 = (i & 15) << 2;
                *(uint2*)(sB_hi + n * 72 + c4) = *(const uint2*)(g_w1t_hi + n * K1P + kb64 + c4);
                *(uint2*)(sB_lo + n * 72 + c4) = *(const uint2*)(g_w1t_lo + n * K1P + kb64 + c4);
            }
        }
        // ---- stage Wi chunk
        if (iv) {
            int kb64 = kb * 64;
            #pragma unroll
            for (int j = 0; j < 2; j++) {
                int i = tid + j * 256;              // 24*16 = 384 uint2
                if (i < 384) {
                    int n = i >> 4, c4 = (i & 15) << 2;
                    *(uint2*)(sWi_hi + n * 72 + c4) = *(const uint2*)(g_wit_hi + n * KIP + kb64 + c4);
                    *(uint2*)(sWi_lo + n * 72 + c4) = *(const uint2*)(g_wit_lo + n * KIP + kb64 + c4);
                }
            }
        }
        __syncthreads();

        // ---- compute
        const int ksm = (kb == 16) ? 2 : 4;   // special chunk: cols 0..18 only
        for (int ks = 0; ks < ksm; ks++) {
            int k0 = ks * 16;
            if (g1) {
                uint32_t a[2][4];
                #pragma unroll
                for (int mt = 0; mt < 2; mt++) {
                    int r = m0 + mt * 16 + (lane & 15);
                    int c = k0 + ((lane >> 4) << 3);
                    ldsm_x4(a[mt], smaddr(sA + r * 72 + c));
                }
                #pragma unroll
                for (int nt = 0; nt < 9; nt++) {
                    uint32_t bh[2], bl[2];
                    int l15 = lane & 15;
                    int nr = n0 + nt * 8 + (l15 & 7);
                    int c = k0 + ((l15 >> 3) << 3);
                    ldsm_x2(bh, smaddr(sB_hi + nr * 72 + c));
                    ldsm_x2(bl, smaddr(sB_lo + nr * 72 + c));
                    #pragma unroll
                    for (int mt = 0; mt < 2; mt++) {
                        mma_f16(acc1[mt][nt], a[mt], bh);
                        mma_f16(acc1[mt][nt], a[mt], bl);
                    }
                }
            }
            if (iv) {
                uint32_t ai[4];
                {
                    int r = mI + (lane & 15);
                    int c = k0 + ((lane >> 4) << 3);
                    ldsm_x4(ai, smaddr(sA + r * 72 + c));
                }
                #pragma unroll
                for (int nt = 0; nt < 3; nt++) {
                    uint32_t bh[2], bl[2];
                    int l15 = lane & 15;
                    int nr = nt * 8 + (l15 & 7);
                    int c = k0 + ((l15 >> 3) << 3);
                    ldsm_x2(bh, smaddr(sWi_hi + nr * 72 + c));
                    ldsm_x2(bl, smaddr(sWi_lo + nr * 72 + c));
                    mma_f16(accI[nt], ai, bh);
                    mma_f16(accI[nt], ai, bl);
                }
            }
        }
    }

    // ---- gemm1 epilogue: hid -> fp16 (ones column at 140 for b2)
    #pragma unroll
    for (int mt = 0; mt < 2; mt++) {
        #pragma unroll
        for (int nt = 0; nt < 9; nt++) {
            int col = n0 + nt * 8 + ((lane & 3) << 1);
            int rb = row0 + m0 + mt * 16 + (lane >> 2);
            #pragma unroll
            for (int h = 0; h < 2; h++) {
                float v0 = acc1[mt][nt][h * 2 + 0];
                float v1 = acc1[mt][nt][h * 2 + 1];
                if (col == 140) v0 = 1.f;
                int row = rb + h * 8;
                *(uint32_t*)(g_hid + (size_t)row * N1P + col) =
                    pack2h(__float2half_rn(v0), __float2half_rn(v1));
            }
        }
    }

    // ---- inv epilogue: logits -> smem, softmax over agents
    #pragma unroll
    for (int nt = 0; nt < 3; nt++) {
        int col = nt * 8 + ((lane & 3) << 1);
        int rl = mI + (lane >> 2);
        sL[rl * 25 + col]           = accI[nt][0];
        sL[rl * 25 + col + 1]       = accI[nt][1];
        sL[(rl + 8) * 25 + col]     = accI[nt][2];
        sL[(rl + 8) * 25 + col + 1] = accI[nt][3];
    }
    __syncthreads();

    if (tid < 72) {
        int f = tid / 18, j = tid - f * 18;
        float vals[32], mx = -1e30f;
        #pragma unroll
        for (int a = 0; a < 32; a++) {
            vals[a] = sL[(f * 32 + a) * 25 + j];
            mx = fmaxf(mx, vals[a]);
        }
        float s = 0.f;
        #pragma unroll
        for (int a = 0; a < 32; a++) { vals[a] = expf(vals[a] - mx); s += vals[a]; }
        float inv = 1.f / s;
        int frame = blockIdx.x * 4 + f;
        if (j < 8) {
            size_t base = OFF_A0 + (size_t)(frame * 32) * 8 + j;
            #pragma unroll
            for (int a = 0; a < 32; a++) out[base + (size_t)a * 8] = vals[a] * inv;
        } else if (j < 14) {
            size_t base = OFF_A1 + (size_t)(frame * 32) * 6 + (j - 8);
            #pragma unroll
            for (int a = 0; a < 32; a++) out[base + (size_t)a * 6] = vals[a] * inv;
        } else {
            size_t base = OFF_A2 + (size_t)(frame * 32) * 4 + (j - 14);
            #pragma unroll
            for (int a = 0; a < 32; a++) out[base + (size_t)a * 4] = vals[a] * inv;
        }
    }
}

// ---------------------------------------------------------------- GEMM2
// pred[65536,256] = [hid|1] @ W2aug  (A single fp16, B split-2)
__global__ __launch_bounds__(256) void gemm2_kernel(float* __restrict__ out)
{
    __shared__ __half sA[128 * 56];
    __shared__ __half sB_hi[64 * 56], sB_lo[64 * 56];

    const int tid = threadIdx.x, lane = tid & 31, w = tid >> 5;
    const int row0 = blockIdx.x * 128;
    const int col0 = blockIdx.y * 64;
    const int m0 = (w >> 1) * 32, n0 = (w & 1) * 32;

    float acc[2][4][4];
    #pragma unroll
    for (int a = 0; a < 2; a++)
        #pragma unroll
        for (int b = 0; b < 4; b++)
            #pragma unroll
            for (int c = 0; c < 4; c++) acc[a][b][c] = 0.f;

    for (int kb = 0; kb < 3; kb++) {
        int kb48 = kb * 48;
        #pragma unroll
        for (int j = 0; j < 6; j++) {       // A: 128*12 uint2
            int i = tid + j * 256;
            int r = i / 12, c4 = (i - r * 12) << 2;
            *(uint2*)(sA + r * 56 + c4) = *(const uint2*)(g_hid + (size_t)(row0 + r) * N1P + kb48 + c4);
        }
        #pragma unroll
        for (int j = 0; j < 3; j++) {       // B: 64*12 uint2 per array
            int i = tid + j * 256;
            int n = i / 12, c4 = (i - n * 12) << 2;
            *(uint2*)(sB_hi + n * 56 + c4) = *(const uint2*)(g_w2t_hi + (size_t)(col0 + n) * K2P + kb48 + c4);
            *(uint2*)(sB_lo + n * 56 + c4) = *(const uint2*)(g_w2t_lo + (size_t)(col0 + n) * K2P + kb48 + c4);
        }
        __syncthreads();

        #pragma unroll
        for (int ks = 0; ks < 3; ks++) {
            int k0 = ks * 16;
            uint32_t a[2][4];
            #pragma unroll
            for (int mt = 0; mt < 2; mt++) {
                int r = m0 + mt * 16 + (lane & 15);
                int c = k0 + ((lane >> 4) << 3);
                ldsm_x4(a[mt], smaddr(sA + r * 56 + c));
            }
            #pragma unroll
            for (int nt = 0; nt < 4; nt++) {
                uint32_t bh[2], bl[2];
                int l15 = lane & 15;
                int nr = n0 + nt * 8 + (l15 & 7);
                int c = k0 + ((l15 >> 3) << 3);
                ldsm_x2(bh, smaddr(sB_hi + nr * 56 + c));
                ldsm_x2(bl, smaddr(sB_lo + nr * 56 + c));
                #pragma unroll
                for (int mt = 0; mt < 2; mt++) {
                    mma_f16(acc[mt][nt], a[mt], bh);
                    mma_f16(acc[mt][nt], a[mt], bl);
                }
            }
        }
        __syncthreads();
    }

    #pragma unroll
    for (int mt = 0; mt < 2; mt++) {
        #pragma unroll
        for (int nt = 0; nt < 4; nt++) {
            int col = col0 + n0 + nt * 8 + ((lane & 3) << 1);
            int rb = row0 + m0 + mt * 16 + (lane >> 2);
            *(float2*)(out + (size_t)rb * OUT2 + col) =
                make_float2(acc[mt][nt][0], acc[mt][nt][1]);
            *(float2*)(out + (size_t)(rb + 8) * OUT2 + col) =
                make_float2(acc[mt][nt][2], acc[mt][nt][3]);
        }
    }
}

// ----------------------------------------------------------------
extern "C" void kernel_launch(void* const* d_in, const int* in_sizes, int n_in,
                              void* d_out, int out_size)
{
    const float* cur  = (const float*)d_in[0];
    const float* nxt  = (const float*)d_in[1];
    const int*   acts = (const int*)  d_in[2];
    const float* W1   = (const float*)d_in[3];
    const float* b1   = (const float*)d_in[4];
    const float* W2   = (const float*)d_in[5];
    const float* b2   = (const float*)d_in[6];
    const float* Wi0  = (const float*)d_in[7];
    const float* Wi1  = (const float*)d_in[9];
    const float* Wi2  = (const float*)d_in[11];
    float* out = (float*)d_out;

    cudaFuncSetAttribute(fused1_kernel, cudaFuncAttributeMaxDynamicSharedMemorySize, 79616);

    prep_kernel<<<(N1P * K1P + 255) / 256, 256>>>(W1, b1, W2, b2, Wi0, Wi1, Wi2);
    fused1_kernel<<<N_ROWS / 128, 256, 79616>>>(cur, nxt, acts, out);
    gemm2_kernel<<<dim3(N_ROWS / 128, OUT2 / 64), 256>>>(out);
}

// round 6
// speedup vs baseline: 13.4722x; 1.3411x over previous
#include <cuda_runtime.h>
#include <cuda_fp16.h>
#include <stdint.h>
#include <math.h>

#define N_FRAMES 2048
#define N_AGENTS 32
#define N_ROWS 65536
#define FEAT 512
#define HID 140
#define OUT2 256

#define OFF_A0 (N_ROWS * OUT2)
#define OFF_A1 (OFF_A0 + N_ROWS * 8)
#define OFF_A2 (OFF_A1 + N_ROWS * 6)

// padded dims
#define K1P 576   // 512 feat + 18 onehot + bias@530 + pad
#define N1P 144   // 140 hid + ones@140 + pad
#define K2P 144
#define KIP 1024  // cur|next
#define NIP 24

// single-fp16 transposed weights
__device__ __align__(16) __half g_w1t[N1P * K1P];     // [n][k]
__device__ __align__(16) __half g_wit[NIP * KIP];     // [n][k]
__device__ __align__(16) __half g_w2t[OUT2 * K2P];    // [n][k]

// ---------------------------------------------------------------- helpers
__device__ __forceinline__ uint32_t smaddr(const void* p) {
    return (uint32_t)__cvta_generic_to_shared(p);
}
__device__ __forceinline__ void ldsm_x4(uint32_t* r, uint32_t a) {
    asm volatile("ldmatrix.sync.aligned.m8n8.x4.shared.b16 {%0,%1,%2,%3}, [%4];"
        : "=r"(r[0]), "=r"(r[1]), "=r"(r[2]), "=r"(r[3]) : "r"(a));
}
__device__ __forceinline__ void ldsm_x2(uint32_t* r, uint32_t a) {
    asm volatile("ldmatrix.sync.aligned.m8n8.x2.shared.b16 {%0,%1}, [%2];"
        : "=r"(r[0]), "=r"(r[1]) : "r"(a));
}
__device__ __forceinline__ void mma_f16(float* d, const uint32_t* a, const uint32_t* b) {
    asm volatile("mma.sync.aligned.m16n8k16.row.col.f32.f16.f16.f32 "
        "{%0,%1,%2,%3}, {%4,%5,%6,%7}, {%8,%9}, {%0,%1,%2,%3};"
        : "+f"(d[0]), "+f"(d[1]), "+f"(d[2]), "+f"(d[3])
        : "r"(a[0]), "r"(a[1]), "r"(a[2]), "r"(a[3]), "r"(b[0]), "r"(b[1]));
}
__device__ __forceinline__ uint32_t pack2h(__half a, __half b) {
    __half2 t; t.x = a; t.y = b;
    return *reinterpret_cast<uint32_t*>(&t);
}

// ---------------------------------------------------------------- prep
__global__ void prep_kernel(
    const float* __restrict__ W1, const float* __restrict__ b1,
    const float* __restrict__ W2, const float* __restrict__ b2,
    const float* __restrict__ Wi0, const float* __restrict__ Wi1,
    const float* __restrict__ Wi2)
{
    int idx = blockIdx.x * 256 + threadIdx.x;
    if (idx < N1P * K1P) {
        int n = idx / K1P, k = idx - n * K1P;
        float v = 0.f;
        if (n < HID) {
            if (k < 530)       v = W1[(size_t)k * HID + n];
            else if (k == 530) v = b1[n];
        }
        g_w1t[idx] = __float2half_rn(v);
    }
    if (idx < OUT2 * K2P) {
        int n = idx / K2P, k = idx - n * K2P;
        float v = 0.f;
        if (k < HID)       v = W2[(size_t)k * OUT2 + n];
        else if (k == HID) v = b2[n];
        g_w2t[idx] = __float2half_rn(v);
    }
    if (idx < NIP * KIP) {
        int n = idx / KIP, k = idx - n * KIP;
        float v = 0.f;
        if (n < 8)        v = Wi0[(size_t)k * 8 + n];
        else if (n < 14)  v = Wi1[(size_t)k * 6 + (n - 8)];
        else if (n < 18)  v = Wi2[(size_t)k * 4 + (n - 14)];
        g_wit[idx] = __float2half_rn(v);
    }
}

// stage 128x64 fp32 feature chunk -> fp16 smem (stride 72 halfs)
__device__ __forceinline__ void stage_feat(
    __half* sA, const float* __restrict__ src, int row0, int c0, int tid)
{
    #pragma unroll
    for (int j = 0; j < 8; j++) {
        int i = tid + j * 256;
        int r = i >> 4, ce = (i & 15) << 2;
        float4 v = *(const float4*)(src + (size_t)(row0 + r) * FEAT + c0 + ce);
        uint2 u;
        u.x = pack2h(__float2half_rn(v.x), __float2half_rn(v.y));
        u.y = pack2h(__float2half_rn(v.z), __float2half_rn(v.w));
        *(uint2*)(sA + r * 72 + ce) = u;
    }
}

// ---------------------------------------------------------------- FUSED ALL
// phase1: hid = [cur|onehot|1] @ W1aug (->smem) and logits = [cur|nxt] @ Wi
// phase2: agent-axis softmax -> out
// phase3: pred = hid(smem) @ W2aug -> out, 4 chunks of 64 cols
// smem: sA @0 (18432) | sB1 @18432 (20736) | sWi @39168 (3456)
//       sL @42624 (12800, fp32 stride 25) | sHid @55424 (128*152*2 = 38912)
//       phase3: sW2 @0 (64*152*2 = 19456, aliases dead sA/sB1)
#define SM_A    0
#define SM_B1   18432
#define SM_WI   39168
#define SM_L    42624
#define SM_HID  55424
#define SM_W2   0
#define SM_TOTAL 94336

__global__ __launch_bounds__(256, 2) void fused_all(
    const float* __restrict__ cur, const float* __restrict__ nxt,
    const int* __restrict__ actions, float* __restrict__ out)
{
    extern __shared__ char smem[];
    __half* sA   = (__half*)(smem + SM_A);
    __half* sB1  = (__half*)(smem + SM_B1);
    __half* sWi  = (__half*)(smem + SM_WI);
    float*  sL   = (float*) (smem + SM_L);
    __half* sHid = (__half*)(smem + SM_HID);
    __half* sW2  = (__half*)(smem + SM_W2);

    const int tid = threadIdx.x, lane = tid & 31, w = tid >> 5;
    const int row0 = blockIdx.x * 128;
    const int m0 = (w >> 1) * 32, n0 = (w & 1) * 72;   // gemm1 warp tile
    const int mI = w * 16;                              // inv warp rows

    // ================= phase 1: gemm1 + inv mainloop =================
    float acc1[2][9][4];
    #pragma unroll
    for (int a = 0; a < 2; a++)
        #pragma unroll
        for (int b = 0; b < 9; b++)
            #pragma unroll
            for (int c = 0; c < 4; c++) acc1[a][b][c] = 0.f;
    float accI[3][4];
    #pragma unroll
    for (int b = 0; b < 3; b++)
        #pragma unroll
        for (int c = 0; c < 4; c++) accI[b][c] = 0.f;

    for (int kb = 0; kb < 17; kb++) {
        if (kb) __syncthreads();
        const bool g1 = (kb < 8) || (kb == 16);
        const bool iv = (kb < 16);

        // ---- stage A
        if (kb < 8) {
            stage_feat(sA, cur, row0, kb * 64, tid);
        } else if (kb < 16) {
            stage_feat(sA, nxt, row0, (kb - 8) * 64, tid);
        } else {
            #pragma unroll
            for (int j = 0; j < 5; j++) {          // zero 18432 B = 1152 uint4
                int i = tid + j * 256;
                if (i < 1152) *(uint4*)(smem + SM_A + i * 16) = make_uint4(0, 0, 0, 0);
            }
            __syncthreads();
            if (tid < 128) {
                int r = tid;
                int f = (row0 + r) >> 5, ag = (row0 + r) & 31;
                int i0 = actions[(f * 3 + 0) * N_AGENTS + ag];
                int i1 = actions[(f * 3 + 1) * N_AGENTS + ag];
                int i2 = actions[(f * 3 + 2) * N_AGENTS + ag];
                __half one = __float2half_rn(1.f);
                sA[r * 72 + i0] = one;
                sA[r * 72 + 8 + i1] = one;
                sA[r * 72 + 14 + i2] = one;
                sA[r * 72 + 18] = one;             // b1 column (k=530)
            }
        }
        // ---- stage B1 chunk (144 x 64 fp16)
        if (g1) {
            int kb64 = (kb < 8) ? kb * 64 : 512;
            #pragma unroll
            for (int j = 0; j < 5; j++) {          // 144*8 = 1152 uint4
                int i = tid + j * 256;
                if (i < 1152) {
                    int n = i >> 3, ce = (i & 7) << 3;
                    *(uint4*)(sB1 + n * 72 + ce) =
                        *(const uint4*)(g_w1t + (size_t)n * K1P + kb64 + ce);
                }
            }
        }
        // ---- stage Wi chunk (24 x 64 fp16)
        if (iv) {
            int kb64 = kb * 64;
            int i = tid;                            // 24*8 = 192 uint4
            if (i < 192) {
                int n = i >> 3, ce = (i & 7) << 3;
                *(uint4*)(sWi + n * 72 + ce) =
                    *(const uint4*)(g_wit + (size_t)n * KIP + kb64 + ce);
            }
        }
        __syncthreads();

        // ---- compute
        const int kmax = (kb == 16) ? 2 : 4;
        for (int ks = 0; ks < kmax; ks++) {
            int k0 = ks * 16;
            if (g1) {
                uint32_t a[2][4];
                #pragma unroll
                for (int mt = 0; mt < 2; mt++) {
                    int r = m0 + mt * 16 + (lane & 15);
                    int c = k0 + ((lane >> 4) << 3);
                    ldsm_x4(a[mt], smaddr(sA + r * 72 + c));
                }
                #pragma unroll
                for (int nt = 0; nt < 9; nt++) {
                    uint32_t b[2];
                    int l15 = lane & 15;
                    int nr = n0 + nt * 8 + (l15 & 7);
                    int c = k0 + ((l15 >> 3) << 3);
                    ldsm_x2(b, smaddr(sB1 + nr * 72 + c));
                    #pragma unroll
                    for (int mt = 0; mt < 2; mt++)
                        mma_f16(acc1[mt][nt], a[mt], b);
                }
            }
            if (iv) {
                uint32_t ai[4];
                {
                    int r = mI + (lane & 15);
                    int c = k0 + ((lane >> 4) << 3);
                    ldsm_x4(ai, smaddr(sA + r * 72 + c));
                }
                #pragma unroll
                for (int nt = 0; nt < 3; nt++) {
                    uint32_t b[2];
                    int l15 = lane & 15;
                    int nr = nt * 8 + (l15 & 7);
                    int c = k0 + ((l15 >> 3) << 3);
                    ldsm_x2(b, smaddr(sWi + nr * 72 + c));
                    mma_f16(accI[nt], ai, b);
                }
            }
        }
    }
    __syncthreads();

    // ================= phase 2: epilogues =================
    // hid -> smem fp16 (ones column at 140)
    #pragma unroll
    for (int mt = 0; mt < 2; mt++) {
        #pragma unroll
        for (int nt = 0; nt < 9; nt++) {
            int col = n0 + nt * 8 + ((lane & 3) << 1);
            int rl = m0 + mt * 16 + (lane >> 2);
            #pragma unroll
            for (int h = 0; h < 2; h++) {
                float v0 = acc1[mt][nt][h * 2 + 0];
                float v1 = acc1[mt][nt][h * 2 + 1];
                if (col == 140) v0 = 1.f;
                *(uint32_t*)(sHid + (rl + h * 8) * 152 + col) =
                    pack2h(__float2half_rn(v0), __float2half_rn(v1));
            }
        }
    }
    // logits -> sL
    #pragma unroll
    for (int nt = 0; nt < 3; nt++) {
        int col = nt * 8 + ((lane & 3) << 1);
        int rl = mI + (lane >> 2);
        sL[rl * 25 + col]           = accI[nt][0];
        sL[rl * 25 + col + 1]       = accI[nt][1];
        sL[(rl + 8) * 25 + col]     = accI[nt][2];
        sL[(rl + 8) * 25 + col + 1] = accI[nt][3];
    }
    __syncthreads();

    // softmax over 32 agents, per frame (4 frames), per logit column
    if (tid < 72) {
        int f = tid / 18, j = tid - f * 18;
        float vals[32], mx = -1e30f;
        #pragma unroll
        for (int a = 0; a < 32; a++) {
            vals[a] = sL[(f * 32 + a) * 25 + j];
            mx = fmaxf(mx, vals[a]);
        }
        float s = 0.f;
        #pragma unroll
        for (int a = 0; a < 32; a++) { vals[a] = expf(vals[a] - mx); s += vals[a]; }
        float inv = 1.f / s;
        int frame = blockIdx.x * 4 + f;
        if (j < 8) {
            size_t base = OFF_A0 + (size_t)(frame * 32) * 8 + j;
            #pragma unroll
            for (int a = 0; a < 32; a++) out[base + (size_t)a * 8] = vals[a] * inv;
        } else if (j < 14) {
            size_t base = OFF_A1 + (size_t)(frame * 32) * 6 + (j - 8);
            #pragma unroll
            for (int a = 0; a < 32; a++) out[base + (size_t)a * 6] = vals[a] * inv;
        } else {
            size_t base = OFF_A2 + (size_t)(frame * 32) * 4 + (j - 14);
            #pragma unroll
            for (int a = 0; a < 32; a++) out[base + (size_t)a * 4] = vals[a] * inv;
        }
    }
    __syncthreads();   // sL dead; sHid ready; sA/sB1 safe to overwrite

    // ================= phase 3: gemm2 from smem hid =================
    // warp tile: 32 rows x 32 cols per 64-col chunk; 4 chunks cover N=256
    const int m2 = (w >> 1) * 32, n2 = (w & 1) * 32;
    for (int c = 0; c < 4; c++) {
        if (c) __syncthreads();
        // stage W2 chunk: rows c*64..c*64+63, k 0..143 -> sW2 stride 152
        #pragma unroll
        for (int j = 0; j < 5; j++) {              // 64*18 = 1152 uint4
            int i = tid + j * 256;
            if (i < 1152) {
                int n = i / 18, t = i - n * 18, ce = t << 3;
                *(uint4*)(sW2 + n * 152 + ce) =
                    *(const uint4*)(g_w2t + (size_t)(c * 64 + n) * K2P + ce);
            }
        }
        __syncthreads();

        float acc[2][4][4];
        #pragma unroll
        for (int a = 0; a < 2; a++)
            #pragma unroll
            for (int b = 0; b < 4; b++)
                #pragma unroll
                for (int q = 0; q < 4; q++) acc[a][b][q] = 0.f;

        #pragma unroll
        for (int ks = 0; ks < 9; ks++) {
            int k0 = ks * 16;
            uint32_t a[2][4];
            #pragma unroll
            for (int mt = 0; mt < 2; mt++) {
                int r = m2 + mt * 16 + (lane & 15);
                int kc = k0 + ((lane >> 4) << 3);
                ldsm_x4(a[mt], smaddr(sHid + r * 152 + kc));
            }
            #pragma unroll
            for (int nt = 0; nt < 4; nt++) {
                uint32_t b[2];
                int l15 = lane & 15;
                int nr = n2 + nt * 8 + (l15 & 7);
                int kc = k0 + ((l15 >> 3) << 3);
                ldsm_x2(b, smaddr(sW2 + nr * 152 + kc));
                #pragma unroll
                for (int mt = 0; mt < 2; mt++)
                    mma_f16(acc[mt][nt], a[mt], b);
            }
        }

        #pragma unroll
        for (int mt = 0; mt < 2; mt++) {
            #pragma unroll
            for (int nt = 0; nt < 4; nt++) {
                int col = c * 64 + n2 + nt * 8 + ((lane & 3) << 1);
                int rb = row0 + m2 + mt * 16 + (lane >> 2);
                *(float2*)(out + (size_t)rb * OUT2 + col) =
                    make_float2(acc[mt][nt][0], acc[mt][nt][1]);
                *(float2*)(out + (size_t)(rb + 8) * OUT2 + col) =
                    make_float2(acc[mt][nt][2], acc[mt][nt][3]);
            }
        }
    }
}

// ----------------------------------------------------------------
extern "C" void kernel_launch(void* const* d_in, const int* in_sizes, int n_in,
                              void* d_out, int out_size)
{
    const float* cur  = (const float*)d_in[0];
    const float* nxt  = (const float*)d_in[1];
    const int*   acts = (const int*)  d_in[2];
    const float* W1   = (const float*)d_in[3];
    const float* b1   = (const float*)d_in[4];
    const float* W2   = (const float*)d_in[5];
    const float* b2   = (const float*)d_in[6];
    const float* Wi0  = (const float*)d_in[7];
    const float* Wi1  = (const float*)d_in[9];
    const float* Wi2  = (const float*)d_in[11];
    float* out = (float*)d_out;

    cudaFuncSetAttribute(fused_all, cudaFuncAttributeMaxDynamicSharedMemorySize, SM_TOTAL);

    prep_kernel<<<(N1P * K1P + 255) / 256, 256>>>(W1, b1, W2, b2, Wi0, Wi1, Wi2);
    fused_all<<<N_ROWS / 128, 256, SM_TOTAL>>>(cur, nxt, acts, out);
}